// round 15
// baseline (speedup 1.0000x reference)
#include <cuda_runtime.h>

#define NC 128
#define EPS 1e-5f
#define RAYS_PER_CTA 8          // 8 warps/CTA, one ray per warp per iteration
#define THREADS (RAYS_PER_CTA * 32)
#define GRID_CTAS 1216          // 8 CTAs/SM on 152 SMs — single persistent wave
#define FULL 0xffffffffu

__global__ __launch_bounds__(THREADS) void pdf_sampler_kernel(
    const float* __restrict__ deltas,
    const float* __restrict__ density,
    const float* __restrict__ bins,
    const float* __restrict__ u,
    float* __restrict__ out,
    int R)
{
    const int lane = threadIdx.x & 31;
    const int wrp  = threadIdx.x >> 5;

    // fit[p] = (slope, intercept): sample = fma(slope, u, intercept)
    __shared__ __align__(16) float2 fit_sh[RAYS_PER_CTA][NC];
    // cfq[q] = (cdf[4q], cdf[4q+1], cdf[4q+2], cdf[4q+3])
    __shared__ __align__(16) float4 cfq_sh[RAYS_PER_CTA][32];

    const int warp_global = blockIdx.x * RAYS_PER_CTA + wrp;
    const int warp_total  = GRID_CTAS * RAYS_PER_CTA;

    for (int ray = warp_global; ray < R; ray += warp_total) {

        const size_t base_c = (size_t)ray * NC;

        // ---- coalesced streaming loads ----
        const float4 dv = __ldcs((const float4*)(deltas  + base_c + 4 * lane));
        const float4 rv = __ldcs((const float4*)(density + base_c + 4 * lane));
        const float4 uv = __ldcs((const float4*)(u       + base_c + 4 * lane));
        const float nearv = __ldg(bins + (size_t)ray * (NC + 1));   // warp-uniform

        // ---- per-lane serial prefixes ----
        const float dd0 = dv.x * rv.x;
        const float dd1 = dv.y * rv.y;
        const float dd2 = dv.z * rv.z;
        const float dd3 = dv.w * rv.w;
        const float pA0 = dd0, pA1 = pA0 + dd1, pA2 = pA1 + dd2, pA3 = pA2 + dd3;
        const float pD0 = dv.x, pD1 = pD0 + dv.y, pD2 = pD1 + dv.z, pD3 = pD2 + dv.w;

        // ---- fused dual warp scan over lane totals ----
        float sA = pA3, sD = pD3;
        #pragma unroll
        for (int o = 1; o < 32; o <<= 1) {
            const float nA = __shfl_up_sync(FULL, sA, o);
            const float nD = __shfl_up_sync(FULL, sD, o);
            if (lane >= o) { sA += nA; sD += nD; }
        }
        const float offA = sA - pA3;
        const float offD = sD - pD3;

        // ---- telescoped cdf: cumsum(w)[i] = 1 - exp(-cumsum(dd)[i]) ----
        const float total = __shfl_sync(FULL, sA, 31);
        const float wsum  = 1.0f - __expf(-total);
        const float pad   = fmaxf(EPS - wsum, 0.0f);
        const float inv   = __fdividef(1.0f, wsum + pad);
        const float ps    = pad * (1.0f / (float)NC);

        const int e = 4 * lane;
        float4 cv;
        cv.x = fminf(1.0f, (1.0f - __expf(-(offA + pA0)) + ps * (float)(e + 1)) * inv);
        cv.y = fminf(1.0f, (1.0f - __expf(-(offA + pA1)) + ps * (float)(e + 2)) * inv);
        cv.z = fminf(1.0f, (1.0f - __expf(-(offA + pA2)) + ps * (float)(e + 3)) * inv);
        cv.w = fminf(1.0f, (1.0f - __expf(-(offA + pA3)) + ps * (float)(e + 4)) * inv);

        const float cprev_raw = __shfl_up_sync(FULL, cv.w, 1);
        const float cprev = (lane == 0) ? 0.0f : cprev_raw;   // cdf[4*lane]

        // ---- per-quad cdf table (1 STS.128) ----
        cfq_sh[wrp][lane] = make_float4(cprev, cv.x, cv.y, cv.z);

        // ---- linear-fit table ----
        const float be0 = nearv + offD;              // bins[e]
        float den0 = cv.x - cprev; den0 = (den0 < EPS) ? 1.0f : den0;
        float den1 = cv.y - cv.x;  den1 = (den1 < EPS) ? 1.0f : den1;
        float den2 = cv.z - cv.y;  den2 = (den2 < EPS) ? 1.0f : den2;
        float den3 = cv.w - cv.z;  den3 = (den3 < EPS) ? 1.0f : den3;
        const float s0 = __fdividef(dv.x, den0);
        const float s1 = __fdividef(dv.y, den1);
        const float s2 = __fdividef(dv.z, den2);
        const float s3 = __fdividef(dv.w, den3);
        const float i0 = fmaf(-s0, cprev, be0);
        const float i1 = fmaf(-s1, cv.x, be0 + pD0);
        const float i2 = fmaf(-s2, cv.y, be0 + pD1);
        const float i3 = fmaf(-s3, cv.z, be0 + pD2);
        *(float4*)(&fit_sh[wrp][e])     = make_float4(s0, i0, s1, i1);
        *(float4*)(&fit_sh[wrp][e + 2]) = make_float4(s2, i2, s3, i3);

        __syncwarp();

        const float2* __restrict__ ft  = fit_sh[wrp];
        const float4* __restrict__ cfq = cfq_sh[wrp];

        // coarse probes (cdf[32/64/96] = cprev of lanes 8/16/24)
        const float g32 = __shfl_sync(FULL, cprev, 8);
        const float g64 = __shfl_sync(FULL, cprev, 16);
        const float g96 = __shfl_sync(FULL, cprev, 24);

        // ---- 4 interleaved searches: SHFL descent + quad LDS + fit LDS ----
        float uu[4] = { uv.x, uv.y, uv.z, uv.w };
        int q[4];

        #pragma unroll
        for (int s = 0; s < 4; s++) {
            const bool l1 = (g64 <= uu[s]);
            q[s] = l1 ? 16 : 0;
            const float v2 = l1 ? g96 : g32;
            if (v2 <= uu[s]) q[s] += 8;
        }
        float pv[4];
        #pragma unroll
        for (int s = 0; s < 4; s++) pv[s] = __shfl_sync(FULL, cprev, q[s] + 4);
        #pragma unroll
        for (int s = 0; s < 4; s++) if (pv[s] <= uu[s]) q[s] += 4;
        #pragma unroll
        for (int s = 0; s < 4; s++) pv[s] = __shfl_sync(FULL, cprev, q[s] + 2);
        #pragma unroll
        for (int s = 0; s < 4; s++) if (pv[s] <= uu[s]) q[s] += 2;
        #pragma unroll
        for (int s = 0; s < 4; s++) pv[s] = __shfl_sync(FULL, cprev, q[s] + 1);
        #pragma unroll
        for (int s = 0; s < 4; s++) if (pv[s] <= uu[s]) q[s] += 1;

        float4 cq[4];
        #pragma unroll
        for (int s = 0; s < 4; s++) cq[s] = cfq[q[s]];

        int pos[4];
        #pragma unroll
        for (int s = 0; s < 4; s++)
            pos[s] = 4 * q[s] + (int)(cq[s].y <= uu[s]) + (int)(cq[s].z <= uu[s]) + (int)(cq[s].w <= uu[s]);

        float2 f[4];
        #pragma unroll
        for (int s = 0; s < 4; s++) f[s] = ft[pos[s]];

        float r[4];
        #pragma unroll
        for (int s = 0; s < 4; s++)
            r[s] = fmaf(f[s].x, uu[s], f[s].y);

        __stcs((float4*)(out + base_c + 4 * lane), make_float4(r[0], r[1], r[2], r[3]));

        __syncwarp();   // protect shared tables before next iteration overwrites
    }
}

extern "C" void kernel_launch(void* const* d_in, const int* in_sizes, int n_in,
                              void* d_out, int out_size) {
    const float* deltas  = (const float*)d_in[0];
    const float* density = (const float*)d_in[1];
    const float* bins    = (const float*)d_in[2];
    const float* u       = (const float*)d_in[3];
    float* out = (float*)d_out;

    int R = in_sizes[0] / NC;               // 131072
    pdf_sampler_kernel<<<GRID_CTAS, THREADS>>>(deltas, density, bins, u, out, R);
}

// round 16
// speedup vs baseline: 1.0332x; 1.0332x over previous
#include <cuda_runtime.h>

#define NC 128
#define EPS 1e-5f
#define RAYS_PER_CTA 8          // 8 warps/CTA, one ray per warp
#define THREADS (RAYS_PER_CTA * 32)
#define FULL 0xffffffffu

__global__ __launch_bounds__(THREADS) void pdf_sampler_kernel(
    const float* __restrict__ deltas,
    const float* __restrict__ density,
    const float* __restrict__ bins,
    const float* __restrict__ u,
    float* __restrict__ out)
{
    const int lane = threadIdx.x & 31;
    const int wrp  = threadIdx.x >> 5;
    const int ray  = blockIdx.x * RAYS_PER_CTA + wrp;

    // fit[p] = (slope, intercept): sample = fma(slope, u, intercept)
    __shared__ __align__(16) float2 fit_sh[RAYS_PER_CTA][NC];
    // cfq[q] = (cdf[4q], cdf[4q+1], cdf[4q+2], cdf[4q+3])
    __shared__ __align__(16) float4 cfq_sh[RAYS_PER_CTA][32];

    const size_t base_c = (size_t)ray * NC;

    // ---- coalesced loads (plain; streaming hints measured neutral-negative) ----
    const float4 dv = *(const float4*)(deltas  + base_c + 4 * lane);
    const float4 rv = *(const float4*)(density + base_c + 4 * lane);
    const float4 uv = *(const float4*)(u       + base_c + 4 * lane);
    const float nearv = bins[(size_t)ray * (NC + 1)];   // warp-uniform

    // ---- per-lane serial prefixes ----
    const float dd0 = dv.x * rv.x;
    const float dd1 = dv.y * rv.y;
    const float dd2 = dv.z * rv.z;
    const float dd3 = dv.w * rv.w;
    const float pA0 = dd0, pA1 = pA0 + dd1, pA2 = pA1 + dd2, pA3 = pA2 + dd3;
    const float pD0 = dv.x, pD1 = pD0 + dv.y, pD2 = pD1 + dv.z, pD3 = pD2 + dv.w;

    // ---- fused dual warp scan, adds packed as f32x2 (1 packed FADD/step) ----
    unsigned long long pk;
    {
        unsigned lo = __float_as_uint(pA3), hi = __float_as_uint(pD3);
        asm("mov.b64 %0, {%1, %2};" : "=l"(pk) : "r"(lo), "r"(hi));
    }
    #pragma unroll
    for (int o = 1; o < 32; o <<= 1) {
        unsigned long long nk = __shfl_up_sync(FULL, pk, o);
        if (lane >= o) {
            asm("add.rn.f32x2 %0, %0, %1;" : "+l"(pk) : "l"(nk));
        }
    }
    float sA, sD;
    {
        unsigned lo, hi;
        asm("mov.b64 {%0, %1}, %2;" : "=r"(lo), "=r"(hi) : "l"(pk));
        sA = __uint_as_float(lo);
        sD = __uint_as_float(hi);
    }
    const float offA = sA - pA3;
    const float offD = sD - pD3;

    // ---- telescoped cdf: cumsum(w)[i] = 1 - exp(-cumsum(dd)[i]) ----
    const float total = __shfl_sync(FULL, sA, 31);
    const float wsum  = 1.0f - __expf(-total);
    const float pad   = fmaxf(EPS - wsum, 0.0f);
    const float inv   = __fdividef(1.0f, wsum + pad);
    const float ps    = pad * (1.0f / (float)NC);

    const int e = 4 * lane;
    float4 cv;
    cv.x = fminf(1.0f, (1.0f - __expf(-(offA + pA0)) + ps * (float)(e + 1)) * inv);
    cv.y = fminf(1.0f, (1.0f - __expf(-(offA + pA1)) + ps * (float)(e + 2)) * inv);
    cv.z = fminf(1.0f, (1.0f - __expf(-(offA + pA2)) + ps * (float)(e + 3)) * inv);
    cv.w = fminf(1.0f, (1.0f - __expf(-(offA + pA3)) + ps * (float)(e + 4)) * inv);

    const float cprev_raw = __shfl_up_sync(FULL, cv.w, 1);
    const float cprev = (lane == 0) ? 0.0f : cprev_raw;   // cdf[4*lane]

    // ---- per-quad cdf table (1 STS.128) ----
    cfq_sh[wrp][lane] = make_float4(cprev, cv.x, cv.y, cv.z);

    // ---- linear-fit table: slope = delta/clamp(den), intercept = b0 - slope*c0 ----
    const float be0 = nearv + offD;              // bins[e]
    float den0 = cv.x - cprev; den0 = (den0 < EPS) ? 1.0f : den0;
    float den1 = cv.y - cv.x;  den1 = (den1 < EPS) ? 1.0f : den1;
    float den2 = cv.z - cv.y;  den2 = (den2 < EPS) ? 1.0f : den2;
    float den3 = cv.w - cv.z;  den3 = (den3 < EPS) ? 1.0f : den3;
    const float s0 = __fdividef(dv.x, den0);
    const float s1 = __fdividef(dv.y, den1);
    const float s2 = __fdividef(dv.z, den2);
    const float s3 = __fdividef(dv.w, den3);
    const float i0 = fmaf(-s0, cprev, be0);
    const float i1 = fmaf(-s1, cv.x, be0 + pD0);
    const float i2 = fmaf(-s2, cv.y, be0 + pD1);
    const float i3 = fmaf(-s3, cv.z, be0 + pD2);
    *(float4*)(&fit_sh[wrp][e])     = make_float4(s0, i0, s1, i1);
    *(float4*)(&fit_sh[wrp][e + 2]) = make_float4(s2, i2, s3, i3);

    __syncwarp();

    const float2* __restrict__ ft  = fit_sh[wrp];
    const float4* __restrict__ cfq = cfq_sh[wrp];

    // coarse probes (cdf[32/64/96] = cprev of lanes 8/16/24)
    const float g32 = __shfl_sync(FULL, cprev, 8);
    const float g64 = __shfl_sync(FULL, cprev, 16);
    const float g96 = __shfl_sync(FULL, cprev, 24);

    // ---- 4 interleaved searches: SHFL descent + quad LDS + fit LDS ----
    float uu[4] = { uv.x, uv.y, uv.z, uv.w };
    int q[4];

    #pragma unroll
    for (int s = 0; s < 4; s++) {
        const bool l1 = (g64 <= uu[s]);
        q[s] = l1 ? 16 : 0;
        const float v2 = l1 ? g96 : g32;
        if (v2 <= uu[s]) q[s] += 8;
    }
    float pv[4];
    #pragma unroll
    for (int s = 0; s < 4; s++) pv[s] = __shfl_sync(FULL, cprev, q[s] + 4);
    #pragma unroll
    for (int s = 0; s < 4; s++) if (pv[s] <= uu[s]) q[s] += 4;
    #pragma unroll
    for (int s = 0; s < 4; s++) pv[s] = __shfl_sync(FULL, cprev, q[s] + 2);
    #pragma unroll
    for (int s = 0; s < 4; s++) if (pv[s] <= uu[s]) q[s] += 2;
    #pragma unroll
    for (int s = 0; s < 4; s++) pv[s] = __shfl_sync(FULL, cprev, q[s] + 1);
    #pragma unroll
    for (int s = 0; s < 4; s++) if (pv[s] <= uu[s]) q[s] += 1;

    // final 2 levels from one quad gather each
    float4 cq[4];
    #pragma unroll
    for (int s = 0; s < 4; s++) cq[s] = cfq[q[s]];

    int pos[4];
    #pragma unroll
    for (int s = 0; s < 4; s++)
        pos[s] = 4 * q[s] + (int)(cq[s].y <= uu[s]) + (int)(cq[s].z <= uu[s]) + (int)(cq[s].w <= uu[s]);

    // ---- single LDS.64 fit gather per sample + FMA ----
    float2 f[4];
    #pragma unroll
    for (int s = 0; s < 4; s++) f[s] = ft[pos[s]];

    float r[4];
    #pragma unroll
    for (int s = 0; s < 4; s++)
        r[s] = fmaf(f[s].x, uu[s], f[s].y);

    *(float4*)(out + base_c + 4 * lane) = make_float4(r[0], r[1], r[2], r[3]);
}

extern "C" void kernel_launch(void* const* d_in, const int* in_sizes, int n_in,
                              void* d_out, int out_size) {
    const float* deltas  = (const float*)d_in[0];
    const float* density = (const float*)d_in[1];
    const float* bins    = (const float*)d_in[2];
    const float* u       = (const float*)d_in[3];
    float* out = (float*)d_out;

    int R = in_sizes[0] / NC;               // 131072
    pdf_sampler_kernel<<<R / RAYS_PER_CTA, THREADS>>>(deltas, density, bins, u, out);
}

// round 17
// speedup vs baseline: 1.0449x; 1.0114x over previous
#include <cuda_runtime.h>

#define NC 128
#define EPS 1e-5f
#define RAYS_PER_CTA 8          // 8 warps/CTA, one ray per warp
#define THREADS (RAYS_PER_CTA * 32)
#define FULL 0xffffffffu

__global__ __launch_bounds__(THREADS) void pdf_sampler_kernel(
    const float* __restrict__ deltas,
    const float* __restrict__ density,
    const float* __restrict__ bins,
    const float* __restrict__ u,
    float* __restrict__ out)
{
    const int lane = threadIdx.x & 31;
    const int wrp  = threadIdx.x >> 5;
    const int ray  = blockIdx.x * RAYS_PER_CTA + wrp;

    // fit[p] = (slope, intercept): sample = fma(slope, u, intercept)
    __shared__ __align__(16) float2 fit_sh[RAYS_PER_CTA][NC];
    // cfq[q] = (cdf[4q], cdf[4q+1], cdf[4q+2], cdf[4q+3])
    __shared__ __align__(16) float4 cfq_sh[RAYS_PER_CTA][32];

    const size_t base_c = (size_t)ray * NC;

    // ---- coalesced plain loads ----
    const float4 dv = *(const float4*)(deltas  + base_c + 4 * lane);
    const float4 rv = *(const float4*)(density + base_c + 4 * lane);
    const float4 uv = *(const float4*)(u       + base_c + 4 * lane);
    const float nearv = bins[(size_t)ray * (NC + 1)];   // warp-uniform

    // ---- per-lane serial prefixes ----
    const float dd0 = dv.x * rv.x;
    const float dd1 = dv.y * rv.y;
    const float dd2 = dv.z * rv.z;
    const float dd3 = dv.w * rv.w;
    const float pA0 = dd0, pA1 = pA0 + dd1, pA2 = pA1 + dd2, pA3 = pA2 + dd3;
    const float pD0 = dv.x, pD1 = pD0 + dv.y, pD2 = pD1 + dv.z, pD3 = pD2 + dv.w;

    // ---- fused dual warp scan over lane totals (plain FADD pair) ----
    float sA = pA3, sD = pD3;
    #pragma unroll
    for (int o = 1; o < 32; o <<= 1) {
        const float nA = __shfl_up_sync(FULL, sA, o);
        const float nD = __shfl_up_sync(FULL, sD, o);
        if (lane >= o) { sA += nA; sD += nD; }
    }
    const float offA = sA - pA3;
    const float offD = sD - pD3;

    // ---- telescoped cdf: cumsum(w)[i] = 1 - exp(-cumsum(dd)[i]) ----
    const float total = __shfl_sync(FULL, sA, 31);
    const float wsum  = 1.0f - __expf(-total);
    const float pad   = fmaxf(EPS - wsum, 0.0f);
    const float inv   = __fdividef(1.0f, wsum + pad);
    const float ps    = pad * (1.0f / (float)NC);

    const int e = 4 * lane;
    float4 cv;
    cv.x = fminf(1.0f, (1.0f - __expf(-(offA + pA0)) + ps * (float)(e + 1)) * inv);
    cv.y = fminf(1.0f, (1.0f - __expf(-(offA + pA1)) + ps * (float)(e + 2)) * inv);
    cv.z = fminf(1.0f, (1.0f - __expf(-(offA + pA2)) + ps * (float)(e + 3)) * inv);
    cv.w = fminf(1.0f, (1.0f - __expf(-(offA + pA3)) + ps * (float)(e + 4)) * inv);

    const float cprev_raw = __shfl_up_sync(FULL, cv.w, 1);
    const float cprev = (lane == 0) ? 0.0f : cprev_raw;   // cdf[4*lane]

    // ---- per-quad cdf table (1 STS.128) ----
    cfq_sh[wrp][lane] = make_float4(cprev, cv.x, cv.y, cv.z);

    // ---- linear-fit table: slope = delta/clamp(den), intercept = b0 - slope*c0 ----
    const float be0 = nearv + offD;              // bins[e]
    float den0 = cv.x - cprev; den0 = (den0 < EPS) ? 1.0f : den0;
    float den1 = cv.y - cv.x;  den1 = (den1 < EPS) ? 1.0f : den1;
    float den2 = cv.z - cv.y;  den2 = (den2 < EPS) ? 1.0f : den2;
    float den3 = cv.w - cv.z;  den3 = (den3 < EPS) ? 1.0f : den3;
    const float s0 = __fdividef(dv.x, den0);
    const float s1 = __fdividef(dv.y, den1);
    const float s2 = __fdividef(dv.z, den2);
    const float s3 = __fdividef(dv.w, den3);
    const float i0 = fmaf(-s0, cprev, be0);
    const float i1 = fmaf(-s1, cv.x, be0 + pD0);
    const float i2 = fmaf(-s2, cv.y, be0 + pD1);
    const float i3 = fmaf(-s3, cv.z, be0 + pD2);
    *(float4*)(&fit_sh[wrp][e])     = make_float4(s0, i0, s1, i1);
    *(float4*)(&fit_sh[wrp][e + 2]) = make_float4(s2, i2, s3, i3);

    __syncwarp();

    const float2* __restrict__ ft  = fit_sh[wrp];
    const float4* __restrict__ cfq = cfq_sh[wrp];

    // coarse probes (cdf[32/64/96] = cprev of lanes 8/16/24)
    const float g32 = __shfl_sync(FULL, cprev, 8);
    const float g64 = __shfl_sync(FULL, cprev, 16);
    const float g96 = __shfl_sync(FULL, cprev, 24);

    // ---- 4 interleaved searches: SHFL descent + quad LDS finals ----
    float uu[4] = { uv.x, uv.y, uv.z, uv.w };
    int q[4];

    #pragma unroll
    for (int s = 0; s < 4; s++) {
        const bool l1 = (g64 <= uu[s]);
        q[s] = l1 ? 16 : 0;
        const float v2 = l1 ? g96 : g32;
        if (v2 <= uu[s]) q[s] += 8;
    }
    float pv[4];
    #pragma unroll
    for (int s = 0; s < 4; s++) pv[s] = __shfl_sync(FULL, cprev, q[s] + 4);
    #pragma unroll
    for (int s = 0; s < 4; s++) if (pv[s] <= uu[s]) q[s] += 4;
    #pragma unroll
    for (int s = 0; s < 4; s++) pv[s] = __shfl_sync(FULL, cprev, q[s] + 2);
    #pragma unroll
    for (int s = 0; s < 4; s++) if (pv[s] <= uu[s]) q[s] += 2;
    #pragma unroll
    for (int s = 0; s < 4; s++) pv[s] = __shfl_sync(FULL, cprev, q[s] + 1);
    #pragma unroll
    for (int s = 0; s < 4; s++) if (pv[s] <= uu[s]) q[s] += 1;

    // final 2 levels from one quad gather each
    float4 cq[4];
    #pragma unroll
    for (int s = 0; s < 4; s++) cq[s] = cfq[q[s]];

    int pos[4];
    #pragma unroll
    for (int s = 0; s < 4; s++)
        pos[s] = 4 * q[s] + (int)(cq[s].y <= uu[s]) + (int)(cq[s].z <= uu[s]) + (int)(cq[s].w <= uu[s]);

    // ---- single LDS.64 fit gather per sample + FMA ----
    float2 f[4];
    #pragma unroll
    for (int s = 0; s < 4; s++) f[s] = ft[pos[s]];

    float r[4];
    #pragma unroll
    for (int s = 0; s < 4; s++)
        r[s] = fmaf(f[s].x, uu[s], f[s].y);

    *(float4*)(out + base_c + 4 * lane) = make_float4(r[0], r[1], r[2], r[3]);
}

extern "C" void kernel_launch(void* const* d_in, const int* in_sizes, int n_in,
                              void* d_out, int out_size) {
    const float* deltas  = (const float*)d_in[0];
    const float* density = (const float*)d_in[1];
    const float* bins    = (const float*)d_in[2];
    const float* u       = (const float*)d_in[3];
    float* out = (float*)d_out;

    int R = in_sizes[0] / NC;               // 131072
    pdf_sampler_kernel<<<R / RAYS_PER_CTA, THREADS>>>(deltas, density, bins, u, out);
}